// round 4
// baseline (speedup 1.0000x reference)
#include <cuda_runtime.h>
#include <cuda_bf16.h>
#include <cstdint>

// DeepRedModel_8589934783 — one CTA per batch element.
// Phases: (1) gather fp32 rows -> bf16 smem + fp32 column sums (batched LDG, MLP=13)
//         (2) G = U I^T via mma.sync bf16 (ldmatrix fragments); col-sums in regs
//             (nt fixed per run), row-sums via per-warp smem scratch (no atomics)
//         (3) softmax over S for user/item coefficients
//         (4) rep = colsum/S + sum_s (w_s - 1/S) * bf16 row   (exact decomposition)

#define B_BATCH 1024
#define S_LEN   200
#define D_DIM   128
#define S_PAD   208
#define ROW_BYTES 272           // 17*16B; rows start banks 4r mod 32 -> LDSM conflict-free
#define NT      13              // 13 tiles of 16 in M and N (208)
#define NTILES  (NT * NT)       // 169
#define NWARPS  16
#define NTHREADS 512

// shared memory byte offsets
#define OFF_U    0
#define OFF_I    (S_PAD * ROW_BYTES)            // 56576
#define OFF_USUM (2 * S_PAD * ROW_BYTES)        // 113152 : 128 f32
#define OFF_ISUM (OFF_USUM + 512)               // 113664
#define OFF_ICOL (OFF_ISUM + 512)               // 114176 : 208 f32 (atomic, rare flushes)
#define OFF_UW   (OFF_ICOL + 832)               // 115008 : 208 f32 softmax weights (user)
#define OFF_IW   (OFF_UW + 832)                 // 115840 : item weights
#define OFF_FP   (OFF_IW + 832)                 // 116672 : 2*2*128 f32 partials
#define OFF_WROW (OFF_FP + 2048)                // 118720 : 16 warps x 208 f32 row scratch
#define SMEM_TOTAL (OFF_WROW + NWARPS * S_PAD * 4)   // 132032 bytes

__device__ __forceinline__ float tanh_fast(float x) {
    float r;
    asm("tanh.approx.f32 %0, %1;" : "=f"(r) : "f"(x));
    return r;
}

__device__ __forceinline__ void mma16816(float c[4], const uint32_t a[4],
                                         uint32_t b0, uint32_t b1) {
    asm volatile(
        "mma.sync.aligned.m16n8k16.row.col.f32.bf16.bf16.f32 "
        "{%0,%1,%2,%3}, {%4,%5,%6,%7}, {%8,%9}, {%0,%1,%2,%3};\n"
        : "+f"(c[0]), "+f"(c[1]), "+f"(c[2]), "+f"(c[3])
        : "r"(a[0]), "r"(a[1]), "r"(a[2]), "r"(a[3]), "r"(b0), "r"(b1));
}

// Non-trans ldmatrix x4: addr row=(lane&15), k-block=(lane>>4)*16B delivers
// r0=(m0-7,k0-7) r1=(m8-15,k0-7) r2=(m0-7,k8-15) r3=(m8-15,k8-15):
// A fragment = (r0,r1,r2,r3); for row-major [n][k] tiles B = (b00,b10,b01,b11).
__device__ __forceinline__ void ldsm_x4(uint32_t r[4], uint32_t saddr) {
    asm volatile("ldmatrix.sync.aligned.m8n8.x4.shared.b16 {%0,%1,%2,%3}, [%4];"
                 : "=r"(r[0]), "=r"(r[1]), "=r"(r[2]), "=r"(r[3]) : "r"(saddr)
                 : "memory");
}

__global__ __launch_bounds__(NTHREADS, 1)
void deepred_kernel(const int* __restrict__ user_nh,
                    const float* __restrict__ user_mask,
                    const int* __restrict__ item_nh,
                    const float* __restrict__ item_mask,
                    const float* __restrict__ table,
                    float* __restrict__ out) {
    extern __shared__ char smem[];
    const int b    = blockIdx.x;
    const int tid  = threadIdx.x;
    const int wid  = tid >> 5;
    const int lane = tid & 31;

    // ---- zero all scratch past the tiles ----
    {
        float* z = (float*)(smem + OFF_USUM);
        const int nz = (SMEM_TOTAL - OFF_USUM) / 4;
        for (int i = tid; i < nz; i += NTHREADS) z[i] = 0.0f;
    }
    __syncthreads();

    // ---- phase 1: gather (fp32 -> bf16 smem, fp32 column sums), MLP=13 ----
    #pragma unroll
    for (int which = 0; which < 2; ++which) {
        const int* nh = (which == 0 ? user_nh : item_nh) + b * S_LEN;
        char* dstBase = smem + (which == 0 ? OFF_U : OFF_I);
        float* csum = (float*)(smem + (which == 0 ? OFF_USUM : OFF_ISUM));

        float4 v[13];
        #pragma unroll
        for (int j = 0; j < 13; ++j) {
            int s = wid + j * NWARPS;          // bijection onto [0,208)
            float4 t = make_float4(0.f, 0.f, 0.f, 0.f);
            if (s < S_LEN) {
                int idx = __ldg(&nh[s]);
                if (idx != 0)                   // padding_idx=0 -> zero row
                    t = __ldg((const float4*)(table + (size_t)idx * D_DIM) + lane);
            }
            v[j] = t;
        }
        float ax = 0.f, ay = 0.f, az = 0.f, aw = 0.f;
        #pragma unroll
        for (int j = 0; j < 13; ++j) {
            int s = wid + j * NWARPS;
            ax += v[j].x; ay += v[j].y; az += v[j].z; aw += v[j].w;
            __nv_bfloat162 h0 = __floats2bfloat162_rn(v[j].x, v[j].y);
            __nv_bfloat162 h1 = __floats2bfloat162_rn(v[j].z, v[j].w);
            uint2 packed = make_uint2(*(uint32_t*)&h0, *(uint32_t*)&h1);
            *(uint2*)(dstBase + s * ROW_BYTES + lane * 8) = packed;
        }
        atomicAdd(&csum[lane * 4 + 0], ax);
        atomicAdd(&csum[lane * 4 + 1], ay);
        atomicAdd(&csum[lane * 4 + 2], az);
        atomicAdd(&csum[lane * 4 + 3], aw);
    }
    __syncthreads();

    // ---- phase 2: tiled bf16 MMA; mt fast-varying, nt fixed per run ----
    {
        float* icol = (float*)(smem + OFF_ICOL);
        float* wrow = (float*)(smem + OFF_WROW) + wid * S_PAD;   // this warp's rows
        const int g  = lane >> 2;
        const int tq = lane & 3;

        const uint32_t ubase = (uint32_t)__cvta_generic_to_shared(smem + OFF_U);
        const uint32_t ibase = (uint32_t)__cvta_generic_to_shared(smem + OFF_I);
        const uint32_t lmoff = (uint32_t)(lane & 15) * ROW_BYTES + (uint32_t)(lane >> 4) * 16;

        const int CHUNK = 11;                 // consecutive t -> nt changes at most once
        int start = wid * CHUNK;
        int end   = min(start + CHUNK, NTILES);

        uint32_t Bv[8][4];
        int cur_n = -1;
        float c0 = 0.f, c1 = 0.f, c2 = 0.f, c3 = 0.f;   // col accumulators

        for (int t = start; t < end; ++t) {
            int mt = t % NT;
            int nt = t / NT;
            if (nt != cur_n) {
                if (cur_n >= 0) {               // flush col sums for finished nt
                    #pragma unroll
                    for (int m = 4; m <= 16; m <<= 1) {
                        c0 += __shfl_xor_sync(0xffffffffu, c0, m);
                        c1 += __shfl_xor_sync(0xffffffffu, c1, m);
                        c2 += __shfl_xor_sync(0xffffffffu, c2, m);
                        c3 += __shfl_xor_sync(0xffffffffu, c3, m);
                    }
                    if (g == 0) {
                        atomicAdd(&icol[cur_n * 16 + tq * 2],     c0);
                        atomicAdd(&icol[cur_n * 16 + tq * 2 + 1], c1);
                        atomicAdd(&icol[cur_n * 16 + 8 + tq * 2],     c2);
                        atomicAdd(&icol[cur_n * 16 + 9 + tq * 2],     c3);
                    }
                    c0 = c1 = c2 = c3 = 0.f;
                }
                cur_n = nt;
                uint32_t bb = ibase + (uint32_t)(nt * 16) * ROW_BYTES + lmoff;
                #pragma unroll
                for (int kk = 0; kk < 8; ++kk)
                    ldsm_x4(Bv[kk], bb + kk * 32);
            }
            uint32_t abase = ubase + (uint32_t)(mt * 16) * ROW_BYTES + lmoff;
            uint32_t A[8][4];
            #pragma unroll
            for (int kk = 0; kk < 8; ++kk)
                ldsm_x4(A[kk], abase + kk * 32);

            float c[2][4] = {{0.f,0.f,0.f,0.f},{0.f,0.f,0.f,0.f}};
            #pragma unroll
            for (int kk = 0; kk < 8; ++kk) {
                mma16816(c[0], A[kk], Bv[kk][0], Bv[kk][2]);
                mma16816(c[1], A[kk], Bv[kk][1], Bv[kk][3]);
            }
            float tn[2][4];
            #pragma unroll
            for (int j = 0; j < 2; ++j)
                #pragma unroll
                for (int q = 0; q < 4; ++q)
                    tn[j][q] = tanh_fast(c[j][q]);

            // col partials (fixed nt): accumulate in registers, no shuffles
            c0 += tn[0][0] + tn[0][2];   // col nt*16 + tq*2
            c1 += tn[0][1] + tn[0][3];   // col nt*16 + tq*2 + 1
            c2 += tn[1][0] + tn[1][2];   // col nt*16 + 8 + tq*2
            c3 += tn[1][1] + tn[1][3];   // col nt*16 + 9 + tq*2

            // row sums for this mt: reduce over tq, RMW into per-warp scratch
            float rlow  = tn[0][0] + tn[0][1] + tn[1][0] + tn[1][1];  // row mt*16+g
            float rhigh = tn[0][2] + tn[0][3] + tn[1][2] + tn[1][3];  // row mt*16+g+8
            rlow  += __shfl_xor_sync(0xffffffffu, rlow, 1);
            rlow  += __shfl_xor_sync(0xffffffffu, rlow, 2);
            rhigh += __shfl_xor_sync(0xffffffffu, rhigh, 1);
            rhigh += __shfl_xor_sync(0xffffffffu, rhigh, 2);
            if (tq == 0) {                       // 8 lanes, 16 distinct addresses
                wrow[mt * 16 + g]     += rlow;
                wrow[mt * 16 + g + 8] += rhigh;
            }
        }
        // final flush
        if (cur_n >= 0) {
            #pragma unroll
            for (int m = 4; m <= 16; m <<= 1) {
                c0 += __shfl_xor_sync(0xffffffffu, c0, m);
                c1 += __shfl_xor_sync(0xffffffffu, c1, m);
                c2 += __shfl_xor_sync(0xffffffffu, c2, m);
                c3 += __shfl_xor_sync(0xffffffffu, c3, m);
            }
            if (g == 0) {
                atomicAdd(&icol[cur_n * 16 + tq * 2],     c0);
                atomicAdd(&icol[cur_n * 16 + tq * 2 + 1], c1);
                atomicAdd(&icol[cur_n * 16 + 8 + tq * 2],     c2);
                atomicAdd(&icol[cur_n * 16 + 9 + tq * 2],     c3);
            }
        }
    }
    __syncthreads();

    // ---- phase 3: softmax over S (warp 0 = user, warp 1 = item) ----
    if (wid < 2) {
        const float* icol = (const float*)(smem + OFF_ICOL);
        const float* wrow = (const float*)(smem + OFF_WROW);
        const float* mask = (wid == 0 ? user_mask : item_mask) + b * S_LEN;
        float* w = (float*)(smem + (wid == 0 ? OFF_UW : OFF_IW));
        float cv[7];
        float mx = -1e30f;
        #pragma unroll
        for (int i = 0; i < 7; ++i) {
            int s = lane + i * 32;
            float v = -1e30f;
            if (s < S_LEN) {
                float raw;
                if (wid == 0) {                 // user: sum the 16 per-warp copies
                    raw = 0.f;
                    #pragma unroll
                    for (int ww = 0; ww < NWARPS; ++ww)
                        raw += wrow[ww * S_PAD + s];
                } else {
                    raw = icol[s];
                }
                v = raw * (1.0f / S_LEN) + mask[s];
            }
            cv[i] = v;
            mx = fmaxf(mx, v);
        }
        #pragma unroll
        for (int m = 16; m >= 1; m >>= 1)
            mx = fmaxf(mx, __shfl_xor_sync(0xffffffffu, mx, m));
        float sum = 0.f;
        #pragma unroll
        for (int i = 0; i < 7; ++i) {
            int s = lane + i * 32;
            float e = 0.f;
            if (s < S_LEN) e = __expf(cv[i] - mx);
            cv[i] = e;
            sum += e;
        }
        #pragma unroll
        for (int m = 16; m >= 1; m >>= 1)
            sum += __shfl_xor_sync(0xffffffffu, sum, m);
        float inv = 1.0f / sum;
        #pragma unroll
        for (int i = 0; i < 7; ++i) {
            int s = lane + i * 32;
            if (s < S_LEN) w[s] = cv[i] * inv;
        }
    }
    __syncthreads();

    // ---- phase 4: rep = colsum/S + sum_s (w_s - 1/S) * bf16 row ----
    {
        const int h     = tid >> 8;          // s-half
        const int which = (tid >> 7) & 1;    // 0=user, 1=item
        const int d     = tid & 127;
        const char* mbase = smem + (which ? OFF_I : OFF_U);
        const float* w = (const float*)(smem + (which ? OFF_IW : OFF_UW));
        float acc = 0.f;
        const int s0 = h * 100;
        #pragma unroll 4
        for (int s = s0; s < s0 + 100; ++s) {
            float wv = w[s] - (1.0f / S_LEN);
            float uv = __bfloat162float(((const __nv_bfloat16*)(mbase + s * ROW_BYTES))[d]);
            acc += wv * uv;
        }
        float* fp = (float*)(smem + OFF_FP);
        fp[(h * 2 + which) * 128 + d] = acc;
        __syncthreads();
        if (h == 0) {
            const float* csum = (const float*)(smem + (which ? OFF_ISUM : OFF_USUM));
            float rep = csum[d] * (1.0f / S_LEN) + fp[which * 128 + d] + fp[(2 + which) * 128 + d];
            out[(size_t)which * B_BATCH * D_DIM + (size_t)b * D_DIM + d] = rep;
        }
    }
}

extern "C" void kernel_launch(void* const* d_in, const int* in_sizes, int n_in,
                              void* d_out, int out_size) {
    // metadata order: users, user_nh, user_mask, items, item_nh, item_mask, emb_table
    const int*   user_nh   = (const int*)d_in[1];
    const float* user_mask = (const float*)d_in[2];
    const int*   item_nh   = (const int*)d_in[4];
    const float* item_mask = (const float*)d_in[5];
    const float* table     = (const float*)d_in[6];

    cudaFuncSetAttribute(deepred_kernel,
                         cudaFuncAttributeMaxDynamicSharedMemorySize, SMEM_TOTAL);
    deepred_kernel<<<B_BATCH, NTHREADS, SMEM_TOTAL>>>(
        user_nh, user_mask, item_nh, item_mask, table, (float*)d_out);
}

// round 10
// speedup vs baseline: 1.0199x; 1.0199x over previous
#include <cuda_runtime.h>
#include <cuda_bf16.h>
#include <cstdint>

// DeepRedModel_8589934783 — one CTA per batch element, 24 warps.
// Phases: (1) gather fp32 rows -> bf16 smem + fp32 column sums (batched LDG)
//         (2) G = U I^T via mma.sync bf16; B fragments cached per nt-run,
//             A fragments transient per k-step; balanced 8/7 tile split
//         (3) parallel cross-warp row reduction + softmax over S
//         (4) rep = colsum/S + sum_s (w_s - 1/S) * bf16 row, vectorized uint4 loads

#define B_BATCH 1024
#define S_LEN   200
#define D_DIM   128
#define S_PAD   208
#define ROW_BYTES 272           // 17*16B; rows start banks 4r mod 32 -> LDSM conflict-free
#define NT      13              // 13 tiles of 16 in M and N (208)
#define NTILES  (NT * NT)       // 169
#define NWARPS  24
#define NTHREADS 768

// shared memory byte offsets
#define OFF_U    0
#define OFF_I    (S_PAD * ROW_BYTES)            // 56576
#define OFF_USUM (2 * S_PAD * ROW_BYTES)        // 113152 : 128 f32
#define OFF_ISUM (OFF_USUM + 512)               // 113664
#define OFF_ICOL (OFF_ISUM + 512)               // 114176 : 208 f32 (atomic, rare flushes)
#define OFF_UROW (OFF_ICOL + 832)               // 115008 : 208 f32 reduced user row sums
#define OFF_UW   (OFF_UROW + 832)               // 115840 : 208 f32 softmax weights (user)
#define OFF_IW   (OFF_UW + 832)                 // 116672 : item weights
#define OFF_WROW (OFF_IW + 832)                 // 117504 : 24 warps x 208 f32 row scratch
                                                //          (reused as phase-4 partials)
#define SMEM_TOTAL (OFF_WROW + NWARPS * S_PAD * 4)   // 137472 bytes

__device__ __forceinline__ float tanh_fast(float x) {
    float r;
    asm("tanh.approx.f32 %0, %1;" : "=f"(r) : "f"(x));
    return r;
}

__device__ __forceinline__ void mma16816(float c[4], const uint32_t a[4],
                                         uint32_t b0, uint32_t b1) {
    asm volatile(
        "mma.sync.aligned.m16n8k16.row.col.f32.bf16.bf16.f32 "
        "{%0,%1,%2,%3}, {%4,%5,%6,%7}, {%8,%9}, {%0,%1,%2,%3};\n"
        : "+f"(c[0]), "+f"(c[1]), "+f"(c[2]), "+f"(c[3])
        : "r"(a[0]), "r"(a[1]), "r"(a[2]), "r"(a[3]), "r"(b0), "r"(b1));
}

// Non-trans ldmatrix x4: addr row=(lane&15), k-block=(lane>>4)*16B delivers
// r0=(m0-7,k0-7) r1=(m8-15,k0-7) r2=(m0-7,k8-15) r3=(m8-15,k8-15):
// A fragment = (r0,r1,r2,r3); for row-major [n][k] tiles B = (b00,b10,b01,b11).
__device__ __forceinline__ void ldsm_x4(uint32_t r[4], uint32_t saddr) {
    asm volatile("ldmatrix.sync.aligned.m8n8.x4.shared.b16 {%0,%1,%2,%3}, [%4];"
                 : "=r"(r[0]), "=r"(r[1]), "=r"(r[2]), "=r"(r[3]) : "r"(saddr)
                 : "memory");
}

__global__ __launch_bounds__(NTHREADS, 1)
void deepred_kernel(const int* __restrict__ user_nh,
                    const float* __restrict__ user_mask,
                    const int* __restrict__ item_nh,
                    const float* __restrict__ item_mask,
                    const float* __restrict__ table,
                    float* __restrict__ out) {
    extern __shared__ char smem[];
    const int b    = blockIdx.x;
    const int tid  = threadIdx.x;
    const int wid  = tid >> 5;
    const int lane = tid & 31;

    // ---- zero all scratch past the tiles ----
    {
        float* z = (float*)(smem + OFF_USUM);
        const int nz = (SMEM_TOTAL - OFF_USUM) / 4;
        for (int i = tid; i < nz; i += NTHREADS) z[i] = 0.0f;
    }
    __syncthreads();

    // ---- phase 1: gather (fp32 -> bf16 smem, fp32 column sums), MLP~9 ----
    #pragma unroll
    for (int which = 0; which < 2; ++which) {
        const int* nh = (which == 0 ? user_nh : item_nh) + b * S_LEN;
        char* dstBase = smem + (which == 0 ? OFF_U : OFF_I);
        float* csum = (float*)(smem + (which == 0 ? OFF_USUM : OFF_ISUM));

        float4 v[9];
        #pragma unroll
        for (int j = 0; j < 9; ++j) {
            int s = wid + j * NWARPS;          // covers [0,208) once each
            float4 t = make_float4(0.f, 0.f, 0.f, 0.f);
            if (s < S_LEN) {
                int idx = __ldg(&nh[s]);
                if (idx != 0)                   // padding_idx=0 -> zero row
                    t = __ldg((const float4*)(table + (size_t)idx * D_DIM) + lane);
            }
            v[j] = t;
        }
        float ax = 0.f, ay = 0.f, az = 0.f, aw = 0.f;
        #pragma unroll
        for (int j = 0; j < 9; ++j) {
            int s = wid + j * NWARPS;
            if (s < S_PAD) {
                ax += v[j].x; ay += v[j].y; az += v[j].z; aw += v[j].w;
                __nv_bfloat162 h0 = __floats2bfloat162_rn(v[j].x, v[j].y);
                __nv_bfloat162 h1 = __floats2bfloat162_rn(v[j].z, v[j].w);
                uint2 packed = make_uint2(*(uint32_t*)&h0, *(uint32_t*)&h1);
                *(uint2*)(dstBase + s * ROW_BYTES + lane * 8) = packed;
            }
        }
        atomicAdd(&csum[lane * 4 + 0], ax);
        atomicAdd(&csum[lane * 4 + 1], ay);
        atomicAdd(&csum[lane * 4 + 2], az);
        atomicAdd(&csum[lane * 4 + 3], aw);
    }
    __syncthreads();

    // ---- phase 2: tiled bf16 MMA; mt fast-varying, nt fixed per run.
    //      Bv cached (32 regs); A transient 4 regs/k-step. Balanced 8/7 split.
    {
        float* icol = (float*)(smem + OFF_ICOL);
        float* wrow = (float*)(smem + OFF_WROW) + wid * S_PAD;   // this warp's rows
        const int g  = lane >> 2;
        const int tq = lane & 3;

        const uint32_t ubase = (uint32_t)__cvta_generic_to_shared(smem + OFF_U);
        const uint32_t ibase = (uint32_t)__cvta_generic_to_shared(smem + OFF_I);
        const uint32_t lmoff = (uint32_t)(lane & 15) * ROW_BYTES + (uint32_t)(lane >> 4) * 16;

        // warp 0: tiles [0,8); warp w>=1: [8+(w-1)*7, 8+w*7)  -> all 24 active
        int start = (wid == 0) ? 0 : 8 + (wid - 1) * 7;
        int end   = (wid == 0) ? 8 : 8 + wid * 7;

        uint32_t Bv[8][4];
        int cur_n = -1;
        float c0 = 0.f, c1 = 0.f, c2 = 0.f, c3 = 0.f;   // col accumulators

        for (int t = start; t < end; ++t) {
            int mt = t % NT;
            int nt = t / NT;
            if (nt != cur_n) {
                if (cur_n >= 0) {               // flush col sums for finished nt
                    #pragma unroll
                    for (int m = 4; m <= 16; m <<= 1) {
                        c0 += __shfl_xor_sync(0xffffffffu, c0, m);
                        c1 += __shfl_xor_sync(0xffffffffu, c1, m);
                        c2 += __shfl_xor_sync(0xffffffffu, c2, m);
                        c3 += __shfl_xor_sync(0xffffffffu, c3, m);
                    }
                    if (g == 0) {
                        atomicAdd(&icol[cur_n * 16 + tq * 2],     c0);
                        atomicAdd(&icol[cur_n * 16 + tq * 2 + 1], c1);
                        atomicAdd(&icol[cur_n * 16 + 8 + tq * 2],     c2);
                        atomicAdd(&icol[cur_n * 16 + 9 + tq * 2],     c3);
                    }
                    c0 = c1 = c2 = c3 = 0.f;
                }
                cur_n = nt;
                uint32_t bb = ibase + (uint32_t)(nt * 16) * ROW_BYTES + lmoff;
                #pragma unroll
                for (int kk = 0; kk < 8; ++kk)
                    ldsm_x4(Bv[kk], bb + kk * 32);
            }
            uint32_t abase = ubase + (uint32_t)(mt * 16) * ROW_BYTES + lmoff;

            float c[2][4] = {{0.f,0.f,0.f,0.f},{0.f,0.f,0.f,0.f}};
            #pragma unroll
            for (int kk = 0; kk < 8; ++kk) {
                uint32_t Av[4];                 // transient A fragment
                ldsm_x4(Av, abase + kk * 32);
                mma16816(c[0], Av, Bv[kk][0], Bv[kk][2]);
                mma16816(c[1], Av, Bv[kk][1], Bv[kk][3]);
            }
            float tn[2][4];
            #pragma unroll
            for (int j = 0; j < 2; ++j)
                #pragma unroll
                for (int q = 0; q < 4; ++q)
                    tn[j][q] = tanh_fast(c[j][q]);

            // col partials (fixed nt): accumulate in registers
            c0 += tn[0][0] + tn[0][2];   // col nt*16 + tq*2
            c1 += tn[0][1] + tn[0][3];   // col nt*16 + tq*2 + 1
            c2 += tn[1][0] + tn[1][2];   // col nt*16 + 8 + tq*2
            c3 += tn[1][1] + tn[1][3];   // col nt*16 + 9 + tq*2

            // row sums for this mt: reduce over tq, RMW into per-warp scratch
            float rlow  = tn[0][0] + tn[0][1] + tn[1][0] + tn[1][1];  // row mt*16+g
            float rhigh = tn[0][2] + tn[0][3] + tn[1][2] + tn[1][3];  // row mt*16+g+8
            rlow  += __shfl_xor_sync(0xffffffffu, rlow, 1);
            rlow  += __shfl_xor_sync(0xffffffffu, rlow, 2);
            rhigh += __shfl_xor_sync(0xffffffffu, rhigh, 1);
            rhigh += __shfl_xor_sync(0xffffffffu, rhigh, 2);
            if (tq == 0) {
                wrow[mt * 16 + g]     += rlow;
                wrow[mt * 16 + g + 8] += rhigh;
            }
        }
        // final flush
        if (cur_n >= 0) {
            #pragma unroll
            for (int m = 4; m <= 16; m <<= 1) {
                c0 += __shfl_xor_sync(0xffffffffu, c0, m);
                c1 += __shfl_xor_sync(0xffffffffu, c1, m);
                c2 += __shfl_xor_sync(0xffffffffu, c2, m);
                c3 += __shfl_xor_sync(0xffffffffu, c3, m);
            }
            if (g == 0) {
                atomicAdd(&icol[cur_n * 16 + tq * 2],     c0);
                atomicAdd(&icol[cur_n * 16 + tq * 2 + 1], c1);
                atomicAdd(&icol[cur_n * 16 + 8 + tq * 2],     c2);
                atomicAdd(&icol[cur_n * 16 + 9 + tq * 2],     c3);
            }
        }
    }
    __syncthreads();

    // ---- phase 3a: parallel reduction of the 24 per-warp row-sum copies ----
    if (tid < S_PAD) {
        const float* wrow = (const float*)(smem + OFF_WROW);
        float r = 0.f;
        #pragma unroll
        for (int ww = 0; ww < NWARPS; ++ww)
            r += wrow[ww * S_PAD + tid];        // stride 208 words: conflict-free
        ((float*)(smem + OFF_UROW))[tid] = r;
    }
    __syncthreads();

    // ---- phase 3b: softmax over S (warp 0 = user, warp 1 = item) ----
    if (wid < 2) {
        const float* rowsum = (const float*)(smem + (wid == 0 ? OFF_UROW : OFF_ICOL));
        const float* mask = (wid == 0 ? user_mask : item_mask) + b * S_LEN;
        float* w = (float*)(smem + (wid == 0 ? OFF_UW : OFF_IW));
        float cv[7];
        float mx = -1e30f;
        #pragma unroll
        for (int i = 0; i < 7; ++i) {
            int s = lane + i * 32;
            float v = -1e30f;
            if (s < S_LEN) v = rowsum[s] * (1.0f / S_LEN) + mask[s];
            cv[i] = v;
            mx = fmaxf(mx, v);
        }
        #pragma unroll
        for (int m = 16; m >= 1; m >>= 1)
            mx = fmaxf(mx, __shfl_xor_sync(0xffffffffu, mx, m));
        float sum = 0.f;
        #pragma unroll
        for (int i = 0; i < 7; ++i) {
            int s = lane + i * 32;
            float e = 0.f;
            if (s < S_LEN) e = __expf(cv[i] - mx);
            cv[i] = e;
            sum += e;
        }
        #pragma unroll
        for (int m = 16; m >= 1; m >>= 1)
            sum += __shfl_xor_sync(0xffffffffu, sum, m);
        float inv = 1.0f / sum;
        #pragma unroll
        for (int i = 0; i < 7; ++i) {
            int s = lane + i * 32;
            if (s < S_LEN) w[s] = cv[i] * inv;
        }
    }
    __syncthreads();

    // ---- phase 4: rep = colsum/S + sum_s (w_s - 1/S) * bf16 row (vectorized) ----
    {
        const int side = (wid < 12) ? 0 : 1;     // 12 warps user, 12 warps item
        const int wIn  = wid - side * 12;
        const char* mbase = smem + (side ? OFF_I : OFF_U);
        const float* w = (const float*)(smem + (side ? OFF_IW : OFF_UW));
        const int half = lane >> 4;              // two rows per warp iteration
        const int seg  = lane & 15;              // 16-byte segment within row

        float acc[8] = {0.f,0.f,0.f,0.f,0.f,0.f,0.f,0.f};
        for (int p = wIn; p < 100; p += 12) {
            int s = 2 * p + half;                // < 200
            float ws = w[s] - (1.0f / S_LEN);
            uint4 rv = *(const uint4*)(mbase + s * ROW_BYTES + seg * 16);
            const __nv_bfloat162* h2 = (const __nv_bfloat162*)&rv;
            #pragma unroll
            for (int q = 0; q < 4; ++q) {
                float2 f = __bfloat1622float2(h2[q]);
                acc[2 * q]     += ws * f.x;
                acc[2 * q + 1] += ws * f.y;
            }
        }
        #pragma unroll
        for (int j = 0; j < 8; ++j)
            acc[j] += __shfl_xor_sync(0xffffffffu, acc[j], 16);

        __syncthreads();                         // wrow reads done; reuse as partials
        float* part = (float*)(smem + OFF_WROW) + wid * 128;
        if (half == 0) {
            *(float4*)(part + seg * 8)     = make_float4(acc[0], acc[1], acc[2], acc[3]);
            *(float4*)(part + seg * 8 + 4) = make_float4(acc[4], acc[5], acc[6], acc[7]);
        }
        __syncthreads();

        if (tid < 256) {
            int oside = tid >> 7, d = tid & 127;
            const float* pb = (const float*)(smem + OFF_WROW) + oside * 12 * 128;
            float r = 0.f;
            #pragma unroll
            for (int ww = 0; ww < 12; ++ww)
                r += pb[ww * 128 + d];
            const float* csum = (const float*)(smem + (oside ? OFF_ISUM : OFF_USUM));
            float rep = csum[d] * (1.0f / S_LEN) + r;
            out[(size_t)oside * B_BATCH * D_DIM + (size_t)b * D_DIM + d] = rep;
        }
    }
}

extern "C" void kernel_launch(void* const* d_in, const int* in_sizes, int n_in,
                              void* d_out, int out_size) {
    // metadata order: users, user_nh, user_mask, items, item_nh, item_mask, emb_table
    const int*   user_nh   = (const int*)d_in[1];
    const float* user_mask = (const float*)d_in[2];
    const int*   item_nh   = (const int*)d_in[4];
    const float* item_mask = (const float*)d_in[5];
    const float* table     = (const float*)d_in[6];

    cudaFuncSetAttribute(deepred_kernel,
                         cudaFuncAttributeMaxDynamicSharedMemorySize, SMEM_TOTAL);
    deepred_kernel<<<B_BATCH, NTHREADS, SMEM_TOTAL>>>(
        user_nh, user_mask, item_nh, item_mask, table, (float*)d_out);
}